// round 1
// baseline (speedup 1.0000x reference)
#include <cuda_runtime.h>
#include <cuda_bf16.h>

// Fixed launch geometry (deterministic partial-sum layout).
#define NBLOCKS 2048
#define NTHREADS 256

__device__ double g_partials[NBLOCKS];

// class(x) = clamp(floor(x), -1, 2) + 1  in {0,1,2,3}
__device__ __forceinline__ int cls_of(float x) {
    float f = floorf(x);
    f = fminf(fmaxf(f, -1.0f), 2.0f);
    return (int)f + 1;
}

__global__ void __launch_bounds__(NTHREADS, 8)
gmgs_reduce_kernel(const float4* __restrict__ pred,
                   const float4* __restrict__ tru,
                   const float* __restrict__ score,
                   long n4)
{
    __shared__ float w[16];
    __shared__ double sred[NTHREADS];

    if (threadIdx.x == 0) {
        float e[16];
        float tot = 0.0f;
        #pragma unroll
        for (int i = 0; i < 16; i++) { e[i] = __expf(-score[i]); tot += e[i]; }
        float inv = 1.0f / tot;
        #pragma unroll
        for (int i = 0; i < 16; i++) w[i] = e[i] * inv;
    }
    __syncthreads();

    double acc = 0.0;
    long stride = (long)gridDim.x * blockDim.x;
    for (long idx = (long)blockIdx.x * blockDim.x + threadIdx.x; idx < n4; idx += stride) {
        float4 p = pred[idx];
        float4 t = tru[idx];

        float d0 = p.x - t.x;
        float d1 = p.y - t.y;
        float d2 = p.z - t.z;
        float d3 = p.w - t.w;

        float w0 = w[cls_of(t.x) * 4 + cls_of(p.x)];
        float w1 = w[cls_of(t.y) * 4 + cls_of(p.y)];
        float w2 = w[cls_of(t.z) * 4 + cls_of(p.z)];
        float w3 = w[cls_of(t.w) * 4 + cls_of(p.w)];

        // Pairwise-combine in fp32 (2 terms), accumulate in fp64 — error safe.
        float s01 = fmaf(d0, d0 * w0, d1 * d1 * w1);
        float s23 = fmaf(d2, d2 * w2, d3 * d3 * w3);
        acc += (double)s01 + (double)s23;
    }

    sred[threadIdx.x] = acc;
    __syncthreads();
    #pragma unroll
    for (int s = NTHREADS / 2; s > 0; s >>= 1) {
        if (threadIdx.x < s) sred[threadIdx.x] += sred[threadIdx.x + s];
        __syncthreads();
    }
    if (threadIdx.x == 0) g_partials[blockIdx.x] = sred[0];
}

__global__ void __launch_bounds__(1024)
gmgs_final_kernel(float* __restrict__ out, double inv_B)
{
    __shared__ double sred[1024];
    double acc = 0.0;
    // NBLOCKS = 2048, 1024 threads -> 2 each, fixed order: deterministic.
    for (int i = threadIdx.x; i < NBLOCKS; i += 1024) acc += g_partials[i];
    sred[threadIdx.x] = acc;
    __syncthreads();
    #pragma unroll
    for (int s = 512; s > 0; s >>= 1) {
        if (threadIdx.x < s) sred[threadIdx.x] += sred[threadIdx.x + s];
        __syncthreads();
    }
    if (threadIdx.x == 0) out[0] = (float)(sred[0] * inv_B);
}

extern "C" void kernel_launch(void* const* d_in, const int* in_sizes, int n_in,
                              void* d_out, int out_size)
{
    const float4* pred  = (const float4*)d_in[0];
    const float4* tru   = (const float4*)d_in[1];
    const float*  score = (const float*)d_in[2];
    float* out = (float*)d_out;

    long n  = (long)in_sizes[0];      // B * T * 1
    long n4 = n / 4;                  // divisible: 524288*48 % 4 == 0
    long B  = n / 48;                 // T = 48 per problem spec

    gmgs_reduce_kernel<<<NBLOCKS, NTHREADS>>>(pred, tru, score, n4);
    gmgs_final_kernel<<<1, 1024>>>(out, 1.0 / (double)B);
}

// round 2
// speedup vs baseline: 1.7361x; 1.7361x over previous
#include <cuda_runtime.h>
#include <cuda_bf16.h>

#define NBLOCKS 2048
#define NTHREADS 256

__device__ float g_partials[NBLOCKS];
__device__ unsigned int g_count = 0;

// class(x) = clamp(floor(x), -1, 2) + 1  in {0,1,2,3}
__device__ __forceinline__ int cls_of(float x) {
    float f = floorf(x);
    f = fminf(fmaxf(f, -1.0f), 2.0f);
    return (int)f + 1;
}

__device__ __forceinline__ float quad_term(const float* __restrict__ w,
                                           float4 p, float4 t) {
    float d0 = p.x - t.x;
    float d1 = p.y - t.y;
    float d2 = p.z - t.z;
    float d3 = p.w - t.w;

    float w0 = w[cls_of(t.x) * 4 + cls_of(p.x)];
    float w1 = w[cls_of(t.y) * 4 + cls_of(p.y)];
    float w2 = w[cls_of(t.z) * 4 + cls_of(p.z)];
    float w3 = w[cls_of(t.w) * 4 + cls_of(p.w)];

    float s01 = fmaf(d0 * d0, w0, d1 * d1 * w1);
    float s23 = fmaf(d2 * d2, w2, d3 * d3 * w3);
    return s01 + s23;
}

__global__ void __launch_bounds__(NTHREADS, 8)
gmgs_fused_kernel(const float4* __restrict__ pred,
                  const float4* __restrict__ tru,
                  const float* __restrict__ score,
                  long n4, float inv_B, float* __restrict__ out)
{
    __shared__ float w[16];
    __shared__ float sred[NTHREADS];
    __shared__ bool s_is_last;

    if (threadIdx.x == 0) {
        float e[16];
        float tot = 0.0f;
        #pragma unroll
        for (int i = 0; i < 16; i++) { e[i] = __expf(-score[i]); tot += e[i]; }
        float inv = 1.0f / tot;
        #pragma unroll
        for (int i = 0; i < 16; i++) w[i] = e[i] * inv;
    }
    __syncthreads();

    const long stride = (long)gridDim.x * blockDim.x;
    float acc0 = 0.0f, acc1 = 0.0f;

    long idx = (long)blockIdx.x * blockDim.x + threadIdx.x;
    // 2-way unrolled grid-stride: 4 independent 16B loads in flight per iter.
    for (; idx + stride < n4; idx += 2 * stride) {
        float4 p0 = pred[idx];
        float4 t0 = tru[idx];
        float4 p1 = pred[idx + stride];
        float4 t1 = tru[idx + stride];
        acc0 += quad_term(w, p0, t0);
        acc1 += quad_term(w, p1, t1);
    }
    if (idx < n4) {
        float4 p0 = pred[idx];
        float4 t0 = tru[idx];
        acc0 += quad_term(w, p0, t0);
    }

    sred[threadIdx.x] = acc0 + acc1;
    __syncthreads();
    #pragma unroll
    for (int s = NTHREADS / 2; s > 0; s >>= 1) {
        if (threadIdx.x < s) sred[threadIdx.x] += sred[threadIdx.x + s];
        __syncthreads();
    }

    if (threadIdx.x == 0) {
        g_partials[blockIdx.x] = sred[0];
        __threadfence();
        unsigned int prev = atomicAdd(&g_count, 1u);
        s_is_last = (prev == (unsigned int)(gridDim.x - 1));
    }
    __syncthreads();

    if (s_is_last) {
        // Deterministic final reduction: fixed-order fixed-tree over g_partials.
        float a = 0.0f;
        #pragma unroll
        for (int i = 0; i < NBLOCKS / NTHREADS; i++)
            a += g_partials[threadIdx.x + i * NTHREADS];
        sred[threadIdx.x] = a;
        __syncthreads();
        #pragma unroll
        for (int s = NTHREADS / 2; s > 0; s >>= 1) {
            if (threadIdx.x < s) sred[threadIdx.x] += sred[threadIdx.x + s];
            __syncthreads();
        }
        if (threadIdx.x == 0) {
            out[0] = sred[0] * inv_B;
            g_count = 0;  // reset for next graph replay
        }
    }
}

extern "C" void kernel_launch(void* const* d_in, const int* in_sizes, int n_in,
                              void* d_out, int out_size)
{
    const float4* pred  = (const float4*)d_in[0];
    const float4* tru   = (const float4*)d_in[1];
    const float*  score = (const float*)d_in[2];
    float* out = (float*)d_out;

    long n  = (long)in_sizes[0];   // B * T
    long n4 = n / 4;
    long B  = n / 48;              // T = 48

    gmgs_fused_kernel<<<NBLOCKS, NTHREADS>>>(pred, tru, score, n4,
                                             (float)(1.0 / (double)B), out);
}

// round 3
// speedup vs baseline: 1.7669x; 1.0177x over previous
#include <cuda_runtime.h>
#include <cuda_bf16.h>

#define NBLOCKS 2048
#define NTHREADS 256
#define NWARPS (NTHREADS / 32)

__device__ float g_partials[NBLOCKS];
__device__ unsigned int g_count = 0;

// class(x) = clamp(floor(x), -1, 2) + 1  in {0,1,2,3}
__device__ __forceinline__ int cls_of(float x) {
    int i = __float2int_rd(x);       // CVT.RMI: floor directly to int
    i = max(i, -1);
    i = min(i, 2);
    return i + 1;
}

__device__ __forceinline__ float quad_term(const float* __restrict__ w,
                                           float4 p, float4 t) {
    float d0 = p.x - t.x;
    float d1 = p.y - t.y;
    float d2 = p.z - t.z;
    float d3 = p.w - t.w;

    float w0 = w[cls_of(t.x) * 4 + cls_of(p.x)];
    float w1 = w[cls_of(t.y) * 4 + cls_of(p.y)];
    float w2 = w[cls_of(t.z) * 4 + cls_of(p.z)];
    float w3 = w[cls_of(t.w) * 4 + cls_of(p.w)];

    float s01 = fmaf(d0 * d0, w0, d1 * d1 * w1);
    float s23 = fmaf(d2 * d2, w2, d3 * d3 * w3);
    return s01 + s23;
}

__global__ void __launch_bounds__(NTHREADS, 6)
gmgs_fused_kernel(const float4* __restrict__ pred,
                  const float4* __restrict__ tru,
                  const float* __restrict__ score,
                  int n4, float inv_B, float* __restrict__ out)
{
    __shared__ float w[16];
    __shared__ float swarp[NWARPS];
    __shared__ bool s_is_last;

    if (threadIdx.x == 0) {
        float e[16];
        float tot = 0.0f;
        #pragma unroll
        for (int i = 0; i < 16; i++) { e[i] = __expf(-score[i]); tot += e[i]; }
        float inv = 1.0f / tot;
        #pragma unroll
        for (int i = 0; i < 16; i++) w[i] = e[i] * inv;
    }
    __syncthreads();

    const int stride = NBLOCKS * NTHREADS;
    float acc0 = 0.0f, acc1 = 0.0f, acc2 = 0.0f, acc3 = 0.0f;

    int i = blockIdx.x * NTHREADS + threadIdx.x;
    // 4-way unrolled grid-stride: 8 independent LDG.128 in flight per iter.
    for (; i + 3 * stride < n4; i += 4 * stride) {
        float4 p0 = pred[i];
        float4 p1 = pred[i + stride];
        float4 p2 = pred[i + 2 * stride];
        float4 p3 = pred[i + 3 * stride];
        float4 t0 = tru[i];
        float4 t1 = tru[i + stride];
        float4 t2 = tru[i + 2 * stride];
        float4 t3 = tru[i + 3 * stride];
        acc0 += quad_term(w, p0, t0);
        acc1 += quad_term(w, p1, t1);
        acc2 += quad_term(w, p2, t2);
        acc3 += quad_term(w, p3, t3);
    }
    for (; i < n4; i += stride) {
        acc0 += quad_term(w, pred[i], tru[i]);
    }

    // Warp reduction (deterministic tree), then cross-warp via smem.
    float v = (acc0 + acc1) + (acc2 + acc3);
    #pragma unroll
    for (int off = 16; off > 0; off >>= 1)
        v += __shfl_xor_sync(0xFFFFFFFFu, v, off);

    int lane = threadIdx.x & 31;
    int warp = threadIdx.x >> 5;
    if (lane == 0) swarp[warp] = v;
    __syncthreads();

    if (threadIdx.x == 0) {
        float bs = 0.0f;
        #pragma unroll
        for (int k = 0; k < NWARPS; k++) bs += swarp[k];
        g_partials[blockIdx.x] = bs;
        __threadfence();
        unsigned int prev = atomicAdd(&g_count, 1u);
        s_is_last = (prev == (unsigned int)(gridDim.x - 1));
    }
    __syncthreads();

    if (s_is_last) {
        // Deterministic final reduction: fixed-order per-thread strided sums,
        // then warp tree, then fixed-order cross-warp sum.
        float a = 0.0f;
        #pragma unroll
        for (int k = 0; k < NBLOCKS / NTHREADS; k++)
            a += g_partials[threadIdx.x + k * NTHREADS];
        #pragma unroll
        for (int off = 16; off > 0; off >>= 1)
            a += __shfl_xor_sync(0xFFFFFFFFu, a, off);
        if (lane == 0) swarp[warp] = a;
        __syncthreads();
        if (threadIdx.x == 0) {
            float tot = 0.0f;
            #pragma unroll
            for (int k = 0; k < NWARPS; k++) tot += swarp[k];
            out[0] = tot * inv_B;
            g_count = 0;  // reset for next graph replay
        }
    }
}

extern "C" void kernel_launch(void* const* d_in, const int* in_sizes, int n_in,
                              void* d_out, int out_size)
{
    const float4* pred  = (const float4*)d_in[0];
    const float4* tru   = (const float4*)d_in[1];
    const float*  score = (const float*)d_in[2];
    float* out = (float*)d_out;

    long n  = (long)in_sizes[0];   // B * T
    int  n4 = (int)(n / 4);
    long B  = n / 48;              // T = 48

    gmgs_fused_kernel<<<NBLOCKS, NTHREADS>>>(pred, tru, score, n4,
                                             (float)(1.0 / (double)B), out);
}

// round 4
// speedup vs baseline: 1.8823x; 1.0653x over previous
#include <cuda_runtime.h>
#include <cuda_bf16.h>

// Exactly one wave: 148 SMs x 6 CTAs/SM (regs=40 @ 256 thr -> occ limit 6).
#define NBLOCKS 888
#define NTHREADS 256
#define NWARPS (NTHREADS / 32)

__device__ float g_partials[NBLOCKS];
__device__ unsigned int g_count = 0;

// class(x) = clamp(floor(x), -1, 2) + 1  in {0,1,2,3}
__device__ __forceinline__ int cls_of(float x) {
    int i = __float2int_rd(x);   // CVT.RMI
    i = max(i, -1);
    i = min(i, 2);
    return i + 1;
}

__device__ __forceinline__ float quad_term(const float* __restrict__ w,
                                           float4 p, float4 t) {
    float d0 = p.x - t.x;
    float d1 = p.y - t.y;
    float d2 = p.z - t.z;
    float d3 = p.w - t.w;

    float w0 = w[cls_of(t.x) * 4 + cls_of(p.x)];
    float w1 = w[cls_of(t.y) * 4 + cls_of(p.y)];
    float w2 = w[cls_of(t.z) * 4 + cls_of(p.z)];
    float w3 = w[cls_of(t.w) * 4 + cls_of(p.w)];

    float s01 = fmaf(d0 * d0, w0, d1 * d1 * w1);
    float s23 = fmaf(d2 * d2, w2, d3 * d3 * w3);
    return s01 + s23;
}

__global__ void __launch_bounds__(NTHREADS, 6)
gmgs_fused_kernel(const float4* __restrict__ pred,
                  const float4* __restrict__ tru,
                  const float* __restrict__ score,
                  int n4, float inv_B, float* __restrict__ out)
{
    __shared__ float w[16];
    __shared__ float swarp[NWARPS];
    __shared__ bool s_is_last;

    if (threadIdx.x == 0) {
        float e[16];
        float tot = 0.0f;
        #pragma unroll
        for (int i = 0; i < 16; i++) { e[i] = __expf(-score[i]); tot += e[i]; }
        float inv = 1.0f / tot;
        #pragma unroll
        for (int i = 0; i < 16; i++) w[i] = e[i] * inv;
    }
    __syncthreads();

    const int stride = NBLOCKS * NTHREADS;
    float acc0 = 0.0f, acc1 = 0.0f, acc2 = 0.0f, acc3 = 0.0f;

    int i = blockIdx.x * NTHREADS + threadIdx.x;
    // 4-way unrolled persistent grid-stride: 8 independent LDG.128 per iter.
    for (; i + 3 * stride < n4; i += 4 * stride) {
        float4 p0 = pred[i];
        float4 p1 = pred[i + stride];
        float4 p2 = pred[i + 2 * stride];
        float4 p3 = pred[i + 3 * stride];
        float4 t0 = tru[i];
        float4 t1 = tru[i + stride];
        float4 t2 = tru[i + 2 * stride];
        float4 t3 = tru[i + 3 * stride];
        acc0 += quad_term(w, p0, t0);
        acc1 += quad_term(w, p1, t1);
        acc2 += quad_term(w, p2, t2);
        acc3 += quad_term(w, p3, t3);
    }
    for (; i < n4; i += stride) {
        acc0 += quad_term(w, pred[i], tru[i]);
    }

    // Warp reduction (deterministic tree), then cross-warp via smem.
    float v = (acc0 + acc1) + (acc2 + acc3);
    #pragma unroll
    for (int off = 16; off > 0; off >>= 1)
        v += __shfl_xor_sync(0xFFFFFFFFu, v, off);

    int lane = threadIdx.x & 31;
    int warp = threadIdx.x >> 5;
    if (lane == 0) swarp[warp] = v;
    __syncthreads();

    if (threadIdx.x == 0) {
        float bs = 0.0f;
        #pragma unroll
        for (int k = 0; k < NWARPS; k++) bs += swarp[k];
        g_partials[blockIdx.x] = bs;
        __threadfence();
        unsigned int prev = atomicAdd(&g_count, 1u);
        s_is_last = (prev == (unsigned int)(gridDim.x - 1));
    }
    __syncthreads();

    if (s_is_last) {
        // Deterministic final reduction over 888 partials.
        float a = 0.0f;
        for (int k = threadIdx.x; k < NBLOCKS; k += NTHREADS)
            a += g_partials[k];
        #pragma unroll
        for (int off = 16; off > 0; off >>= 1)
            a += __shfl_xor_sync(0xFFFFFFFFu, a, off);
        if (lane == 0) swarp[warp] = a;
        __syncthreads();
        if (threadIdx.x == 0) {
            float tot = 0.0f;
            #pragma unroll
            for (int k = 0; k < NWARPS; k++) tot += swarp[k];
            out[0] = tot * inv_B;
            g_count = 0;  // reset for next graph replay
        }
    }
}

extern "C" void kernel_launch(void* const* d_in, const int* in_sizes, int n_in,
                              void* d_out, int out_size)
{
    const float4* pred  = (const float4*)d_in[0];
    const float4* tru   = (const float4*)d_in[1];
    const float*  score = (const float*)d_in[2];
    float* out = (float*)d_out;

    long n  = (long)in_sizes[0];   // B * T
    int  n4 = (int)(n / 4);
    long B  = n / 48;              // T = 48

    gmgs_fused_kernel<<<NBLOCKS, NTHREADS>>>(pred, tru, score, n4,
                                             (float)(1.0 / (double)B), out);
}